// round 10
// baseline (speedup 1.0000x reference)
#include <cuda_runtime.h>
#include <cuda_fp16.h>
#include <stdint.h>

// HybridMixSTEDecoder: 5 disjoint-group GEMMs (27648x512 @ 512xN_i) + bias,
// scattered into out[b, tp*9+p, joint, c]. Groups disjoint -> count/div identity.
//
// Single-pass fp16 mma.sync (A, B RN-rounded fp16, fp32 accum; rel_err ~3e-4).
// 4-stage cp.async pipeline, K-chunks of 32, wait_group 2 -> 3 chunks (~112KB)
// in flight per SM. One 512-thread CTA per SM, M-tile 256.
// Grid (variant, m-block): CTAs sharing token rows are schedule-adjacent.

// Padded group rows: g0..g4 = 88,88,144,88,88 -> 496 rows of 512 fp16.
static __device__ __align__(16) __half g_Bh[496 * 512];

// ---------------- helpers ----------------
static __device__ __forceinline__ uint32_t s2u(const void* p) {
    uint32_t a;
    asm("{ .reg .u64 t; cvta.to.shared.u64 t, %1; cvt.u32.u64 %0, t; }"
        : "=r"(a) : "l"(p));
    return a;
}
static __device__ __forceinline__ uint32_t f16x2_rn(float lo, float hi) {
    uint32_t r; asm("cvt.rn.f16x2.f32 %0, %1, %2;" : "=r"(r) : "f"(hi), "f"(lo));
    return r;  // low half = lo, high half = hi
}
static __device__ __forceinline__ float4 lds128(uint32_t a) {
    float4 v;
    asm volatile("ld.shared.v4.f32 {%0,%1,%2,%3}, [%4];"
        : "=f"(v.x), "=f"(v.y), "=f"(v.z), "=f"(v.w) : "r"(a));
    return v;
}
static __device__ __forceinline__ void ldsm_x4(uint32_t* r, uint32_t addr) {
    asm volatile("ldmatrix.sync.aligned.m8n8.x4.shared.b16 {%0,%1,%2,%3}, [%4];"
        : "=r"(r[0]), "=r"(r[1]), "=r"(r[2]), "=r"(r[3]) : "r"(addr));
}
static __device__ __forceinline__ void ldsm_x2(uint32_t* r, uint32_t addr) {
    asm volatile("ldmatrix.sync.aligned.m8n8.x2.shared.b16 {%0,%1}, [%2];"
        : "=r"(r[0]), "=r"(r[1]) : "r"(addr));
}
static __device__ __forceinline__ void mma_f16(float* d, const uint32_t* a,
                                               const uint32_t* b) {
    asm volatile(
        "mma.sync.aligned.m16n8k16.row.col.f32.f16.f16.f32 "
        "{%0,%1,%2,%3}, {%4,%5,%6,%7}, {%8,%9}, {%0,%1,%2,%3};"
        : "+f"(d[0]), "+f"(d[1]), "+f"(d[2]), "+f"(d[3])
        : "r"(a[0]), "r"(a[1]), "r"(a[2]), "r"(a[3]), "r"(b[0]), "r"(b[1]));
}
static __device__ __forceinline__ void cp16(uint32_t dst, const void* src, int pred) {
    asm volatile(
        "{\n\t.reg .pred p;\n\tsetp.ne.b32 p, %0, 0;\n\t"
        "@p cp.async.cg.shared.global [%1], [%2], 16;\n\t}"
        :: "r"(pred), "r"(dst), "l"(src));
}

// ---------------- prep: W (f32) -> fp16, [n][512] with per-16k permute ------
// Thread handles 4 consecutive k (o = k&15 in {0,4,8,12}, t = o>>2):
//   halves (k,k+1)   -> eff positions (2t, 2t+1)
//   halves (k+2,k+3) -> eff positions (2t+8, 2t+9)
__global__ void __launch_bounds__(256) prep_B(
    const float* __restrict__ W0, const float* __restrict__ W1,
    const float* __restrict__ W2, const float* __restrict__ W3,
    const float* __restrict__ W4)
{
    int idx = blockIdx.x * 256 + threadIdx.x;   // one thread per (grow, k4)
    if (idx >= 496 * 128) return;
    int grow = idx >> 7;
    int k = (idx & 127) << 2;
    int g, n;
    if      (grow <  88) { g = 0; n = grow;       }
    else if (grow < 176) { g = 1; n = grow -  88; }
    else if (grow < 320) { g = 2; n = grow - 176; }
    else if (grow < 408) { g = 3; n = grow - 320; }
    else                 { g = 4; n = grow - 408; }
    const float* Wg = (g == 0) ? W0 : (g == 1) ? W1 : (g == 2) ? W2
                    : (g == 3) ? W3 : W4;
    int Ng = (g == 2) ? 135 : 81;

    float4 v = make_float4(0.f, 0.f, 0.f, 0.f);
    if (n < Ng) v = *(const float4*)(Wg + n * 512 + k);

    uint32_t h01 = f16x2_rn(v.x, v.y);
    uint32_t h23 = f16x2_rn(v.z, v.w);
    uint32_t* dst = (uint32_t*)g_Bh + grow * 256 + ((k & ~15) >> 1) + ((k >> 2) & 3);
    dst[0] = h01;   // eff (2t, 2t+1)
    dst[4] = h23;   // eff (2t+8, 2t+9)
}

// ---------------- fused core ----------------
// Smem: 4 A stages (raw f32, 256 rows x 128B, phys_u = u ^ ((row&1)<<2)),
// then 4 B stages (fp16, row pairs packed in 128B lines,
// phys = ((h<<2)|u) ^ (line&3)).
template<int NPAD, int GS, int CO>
static __device__ __forceinline__ void decode_core(
    const float* __restrict__ tokens,
    const __half* __restrict__ BhT,
    const float* __restrict__ bias,
    float* __restrict__ out,
    int gidx, int jb3)
{
    constexpr int NT    = NPAD / 8;
    constexpr int PAIRS = NT / 2;
    constexpr int ODD   = NT & 1;
    constexpr int NREAL = (GS == 5) ? 135 : 81;
    constexpr int AB    = 32768;               // A stage bytes (256 x 128B)
    constexpr int BOFF  = 4 * AB;              // B region base
    constexpr int BBS   = NPAD * 64;           // B stage bytes
    constexpr int NBOPS = NPAD * 4;            // B cp.async 16B ops per stage

    extern __shared__ char smem[];
    const uint32_t su = s2u(smem);

    const int tid  = threadIdx.x;
    const int wid  = tid >> 5;
    const int lane = tid & 31;

    const int m0 = blockIdx.y * 256;
    const float* Abase = tokens + (size_t)m0 * 2560 + gidx * 512;

    // ---- A producer geometry: 4 iters, row = (tid>>3) + 64*i, u = tid&7 ----
    const int prow = tid >> 3;
    const int pu   = tid & 7;
    const float* asrc0 = Abase + (size_t)prow * 2560 + pu * 4;
    const uint32_t adst0 = su + (uint32_t)(prow * 128
                         + ((pu ^ ((prow & 1) << 2)) << 4));

    // ---- B producer geometry: one shot, n = tid>>2, q = tid&3 ----
    const int bn = tid >> 2;
    const int bq = tid & 3;
    const int bvalid = tid < NBOPS;
    const __half* bsrc0 = BhT + bn * 512 + bq * 8;
    const uint32_t bdst0 = su + BOFF + (uint32_t)((bn >> 1) * 128
                         + (((((bn & 1) << 2) | bq) ^ ((bn >> 1) & 3)) << 4));

    // ---- A consumer geometry (LDS.128) ----
    const int r1  = 16 * wid + (lane >> 2);
    const int tig = lane & 3;
    const int xr  = (r1 & 1) << 2;
    const uint32_t ac1 = su + (uint32_t)(r1 * 128);

    // ---- B consumer geometry (ldmatrix, packed row pairs) ----
    const int rBo = (lane & 7) + ((lane & 16) ? 8 : 0);
    const int kuB = (lane >> 3) & 1;
    const int lh  = rBo >> 1;            // line within 8-line tile
    const int hb  = (rBo & 1) << 2;      // half select bit
    const int bx  = lh & 3;              // xor term (constant per lane)
    const int lh2 = (lane & 7) >> 1;     // for the odd x2 tile
    const int hb2 = ((lane & 7) & 1) << 2;
    const int bx2 = lh2 & 3;

    float acc[NT][4];
    #pragma unroll
    for (int t = 0; t < NT; t++)
        #pragma unroll
        for (int q = 0; q < 4; q++) acc[t][q] = 0.f;

    // ---- prologue: chunks 0,1,2 issued as 3 groups ----
    #pragma unroll
    for (int c = 0; c < 3; c++) {
        #pragma unroll
        for (int i = 0; i < 4; i++)
            cp16(adst0 + c * AB + i * 8192,
                 asrc0 + (size_t)i * 163840 + c * 32, 1);
        cp16(bdst0 + c * BBS, bsrc0 + c * 32, bvalid);
        asm volatile("cp.async.commit_group;" ::: "memory");
    }

    #pragma unroll 1
    for (int kc = 0; kc < 16; kc++) {
        const int s = kc & 3;

        // chunk kc ready when <=2 groups pending (one group per iteration)
        asm volatile("cp.async.wait_group 2;" ::: "memory");
        __syncthreads();

        // issue chunk kc+3 into stage (kc+3)&3 (readers done: it held kc-1)
        {
            const int c = kc + 3;
            const int pred = (c < 16);
            const int s2 = c & 3;
            #pragma unroll
            for (int i = 0; i < 4; i++)
                cp16(adst0 + s2 * AB + i * 8192,
                     asrc0 + (size_t)i * 163840 + c * 32, pred);
            cp16(bdst0 + s2 * BBS, bsrc0 + c * 32, pred && bvalid);
            asm volatile("cp.async.commit_group;" ::: "memory");
        }

        // MMA on stage s
        const uint32_t aS    = ac1 + (uint32_t)(s * AB);
        const uint32_t bBase = su + BOFF + s * BBS;
        #pragma unroll
        for (int j = 0; j < 2; j++) {
            // A fragment: LDS f32 + convert (k-permuted layout matches B)
            uint32_t u1 = (uint32_t)(((4 * j + tig) ^ xr) << 4);
            float4 v1 = lds128(aS + u1);
            float4 v2 = lds128(aS + 1024 + u1);    // row r1+8 (same parity)
            uint32_t ah[4];
            ah[0] = f16x2_rn(v1.x, v1.y);
            ah[2] = f16x2_rn(v1.z, v1.w);
            ah[1] = f16x2_rn(v2.x, v2.y);
            ah[3] = f16x2_rn(v2.z, v2.w);
            // B fragments + MMAs
            const int u = 2 * j + kuB;
            const uint32_t bo = (uint32_t)(lh * 128 + (((hb | u) ^ bx) << 4));
            #pragma unroll
            for (int p = 0; p < PAIRS; p++) {
                uint32_t bh[4];
                ldsm_x4(bh, bBase + p * 1024 + bo);
                mma_f16(acc[2 * p],     ah, bh);
                mma_f16(acc[2 * p + 1], ah, bh + 2);
            }
            if (ODD) {
                uint32_t bo2 = (uint32_t)(PAIRS * 1024 + lh2 * 128
                             + (((hb2 | u) ^ bx2) << 4));
                uint32_t bh[2];
                ldsm_x2(bh, bBase + bo2);
                mma_f16(acc[NT - 1], ah, bh);
            }
        }
    }

    // ---- epilogue: bias + scatter ----
    const int g = lane >> 2;

    int   coff[NT][2];
    float cb[NT][2];
    #pragma unroll
    for (int t = 0; t < NT; t++) {
        #pragma unroll
        for (int h = 0; h < 2; h++) {
            int o = CO + 8 * t + 2 * tig + h;
            if (o < NREAL) {
                int p   = o / (GS * 3);
                int rem = o - p * (GS * 3);
                int joff = (GS == 5) ? ((rem < 3) ? rem : rem + 18) : (jb3 + rem);
                coff[t][h] = p * 51 + joff;
                cb[t][h]   = bias[o];
            } else {
                coff[t][h] = -1;
                cb[t][h]   = 0.f;
            }
        }
    }

    #pragma unroll
    for (int half = 0; half < 2; half++) {
        int m  = m0 + 16 * wid + g + 8 * half;
        int b  = m / 27;
        int tp = m - b * 27;
        size_t obase = (size_t)b * 12393 + (size_t)tp * 459;
        #pragma unroll
        for (int t = 0; t < NT; t++) {
            float v0 = acc[t][2 * half];
            float v1 = acc[t][2 * half + 1];
            if (coff[t][0] >= 0) out[obase + coff[t][0]] = v0 + cb[t][0];
            if (coff[t][1] >= 0) out[obase + coff[t][1]] = v1 + cb[t][1];
        }
    }
}

// One fused kernel. blockIdx.x = variant: 0..3 -> groups 0,1,3,4 (NPAD=88);
// 4,5 -> group 2 halves (NPAD=72). blockIdx.y = m-block of 256 rows (same
// token rows across all 6 variants -> L2 reuse).
__global__ void __launch_bounds__(512, 1) dec_all(
    const float* __restrict__ tokens,
    const float* __restrict__ b0, const float* __restrict__ b1,
    const float* __restrict__ b2, const float* __restrict__ b3,
    const float* __restrict__ b4,
    float* __restrict__ out)
{
    int y = blockIdx.x;
    if (y < 4) {
        int rowbase, gidx, jb3;
        const float* bias;
        switch (y) {
            case 0:  rowbase = 0;   gidx = 0; jb3 = 3;  bias = b0; break;
            case 1:  rowbase = 88;  gidx = 1; jb3 = 12; bias = b1; break;
            case 2:  rowbase = 320; gidx = 3; jb3 = 33; bias = b3; break;
            default: rowbase = 408; gidx = 4; jb3 = 42; bias = b4; break;
        }
        decode_core<88, 3, 0>(tokens, g_Bh + rowbase * 512, bias, out, gidx, jb3);
    } else if (y == 4) {
        decode_core<72, 5, 0>(tokens, g_Bh + 176 * 512, b2, out, 2, 0);
    } else {
        decode_core<72, 5, 72>(tokens, g_Bh + 248 * 512, b2, out, 2, 0);
    }
}

extern "C" void kernel_launch(void* const* d_in, const int* in_sizes, int n_in,
                              void* d_out, int out_size) {
    const float* tokens = (const float*)d_in[0];
    const float* W[5];
    const float* B[5];
    for (int i = 0; i < 5; i++) {
        W[i] = (const float*)d_in[1 + 2 * i];
        B[i] = (const float*)d_in[2 + 2 * i];
    }
    float* out = (float*)d_out;

    // dyn smem: 4 A stages (32KB) + 4 B stages (<=5632B) = 153600 B
    const int smem_sz = 4 * 32768 + 4 * 88 * 64;
    cudaFuncSetAttribute(dec_all, cudaFuncAttributeMaxDynamicSharedMemorySize, smem_sz);

    prep_B<<<(496 * 128 + 255) / 256, 256>>>(W[0], W[1], W[2], W[3], W[4]);
    dec_all<<<dim3(6, 108), 512, smem_sz>>>(tokens, B[0], B[1], B[2], B[3], B[4], out);
}

// round 11
// speedup vs baseline: 1.2525x; 1.2525x over previous
#include <cuda_runtime.h>
#include <cuda_fp16.h>
#include <stdint.h>

// HybridMixSTEDecoder: 5 disjoint-group GEMMs (27648x512 @ 512xN_i) + bias,
// scattered into out[b, tp*9+p, joint, c]. Groups disjoint -> count/div identity.
//
// Single-pass fp16 mma.sync (A, B RN-rounded fp16, fp32 accum; rel_err ~3e-4).
// B (<=90KB) loaded into smem ONCE at start -> the k-mainloop has ZERO
// barriers and ZERO cp.async: A streams through full-chunk register buffers
// (compile-time indices, 1-chunk lookahead), warps self-pace on their own
// LDG scoreboards. Grid (variant, m-block) keeps token rows schedule-adjacent.

// Padded group rows: g0..g4 = 88,88,144,88,88 -> 496 rows of 512 fp16.
static __device__ __align__(16) __half g_Bh[496 * 512];

// ---------------- helpers ----------------
static __device__ __forceinline__ uint32_t s2u(const void* p) {
    uint32_t a;
    asm("{ .reg .u64 t; cvta.to.shared.u64 t, %1; cvt.u32.u64 %0, t; }"
        : "=r"(a) : "l"(p));
    return a;
}
static __device__ __forceinline__ uint32_t f16x2_rn(float lo, float hi) {
    uint32_t r; asm("cvt.rn.f16x2.f32 %0, %1, %2;" : "=r"(r) : "f"(hi), "f"(lo));
    return r;  // low half = lo, high half = hi
}
static __device__ __forceinline__ void ldsm_x4(uint32_t* r, uint32_t addr) {
    asm volatile("ldmatrix.sync.aligned.m8n8.x4.shared.b16 {%0,%1,%2,%3}, [%4];"
        : "=r"(r[0]), "=r"(r[1]), "=r"(r[2]), "=r"(r[3]) : "r"(addr));
}
static __device__ __forceinline__ void ldsm_x2(uint32_t* r, uint32_t addr) {
    asm volatile("ldmatrix.sync.aligned.m8n8.x2.shared.b16 {%0,%1}, [%2];"
        : "=r"(r[0]), "=r"(r[1]) : "r"(addr));
}
static __device__ __forceinline__ void mma_f16(float* d, const uint32_t* a,
                                               const uint32_t* b) {
    asm volatile(
        "mma.sync.aligned.m16n8k16.row.col.f32.f16.f16.f32 "
        "{%0,%1,%2,%3}, {%4,%5,%6,%7}, {%8,%9}, {%0,%1,%2,%3};"
        : "+f"(d[0]), "+f"(d[1]), "+f"(d[2]), "+f"(d[3])
        : "r"(a[0]), "r"(a[1]), "r"(a[2]), "r"(a[3]), "r"(b[0]), "r"(b[1]));
}
static __device__ __forceinline__ void cp16(uint32_t dst, const void* src) {
    asm volatile("cp.async.cg.shared.global [%0], [%1], 16;"
        :: "r"(dst), "l"(src));
}

// ---------------- prep: W (f32) -> fp16, [n][512] with per-16k permute ------
// Thread handles 4 consecutive k (o = k&15 in {0,4,8,12}, t = o>>2):
//   halves (k,k+1)   -> eff positions (2t, 2t+1)
//   halves (k+2,k+3) -> eff positions (2t+8, 2t+9)
__global__ void __launch_bounds__(256) prep_B(
    const float* __restrict__ W0, const float* __restrict__ W1,
    const float* __restrict__ W2, const float* __restrict__ W3,
    const float* __restrict__ W4)
{
    int idx = blockIdx.x * 256 + threadIdx.x;   // one thread per (grow, k4)
    if (idx >= 496 * 128) return;
    int grow = idx >> 7;
    int k = (idx & 127) << 2;
    int g, n;
    if      (grow <  88) { g = 0; n = grow;       }
    else if (grow < 176) { g = 1; n = grow -  88; }
    else if (grow < 320) { g = 2; n = grow - 176; }
    else if (grow < 408) { g = 3; n = grow - 320; }
    else                 { g = 4; n = grow - 408; }
    const float* Wg = (g == 0) ? W0 : (g == 1) ? W1 : (g == 2) ? W2
                    : (g == 3) ? W3 : W4;
    int Ng = (g == 2) ? 135 : 81;

    float4 v = make_float4(0.f, 0.f, 0.f, 0.f);
    if (n < Ng) v = *(const float4*)(Wg + n * 512 + k);

    uint32_t h01 = f16x2_rn(v.x, v.y);
    uint32_t h23 = f16x2_rn(v.z, v.w);
    uint32_t* dst = (uint32_t*)g_Bh + grow * 256 + ((k & ~15) >> 1) + ((k >> 2) & 3);
    dst[0] = h01;   // eff (2t, 2t+1)
    dst[4] = h23;   // eff (2t+8, 2t+9)
}

// ---------------- fused core ----------------
// Smem: 8 B chunk-tiles of NPAD*128 bytes (whole B for this variant).
// Tile layout: row n = 128B (one 64-k chunk), XOR swizzle on 16B units.
template<int NPAD, int GS, int CO>
static __device__ __forceinline__ void decode_core(
    const float* __restrict__ tokens,
    const __half* __restrict__ BhT,
    const float* __restrict__ bias,
    float* __restrict__ out,
    int gidx, int jb3)
{
    constexpr int NT    = NPAD / 8;
    constexpr int PAIRS = NT / 2;
    constexpr int ODD   = NT & 1;
    constexpr int NREAL = (GS == 5) ? 135 : 81;
    constexpr int BB    = NPAD * 128;          // bytes per chunk tile
    constexpr int CPIT  = NPAD / 4;            // = NPAD*64/256 cp16 per thread

    extern __shared__ char smem[];
    const uint32_t su = s2u(smem);

    const int tid  = threadIdx.x;
    const int wid  = tid >> 5;
    const int lane = tid & 31;

    const int m0 = blockIdx.y * 128;

    // A direct-load geometry with the k-permute: lane (r = lane>>2, tig = lane&3)
    // loads float4 at (row r, k = 16j + 4*tig) and (row r+8, same k).
    const float* aw = tokens
        + (size_t)(m0 + 16 * wid + (lane >> 2)) * 2560
        + gidx * 512 + (lane & 3) * 4;

    // ldmatrix B geometry
    const int rBo = (lane & 7) + ((lane & 16) ? 8 : 0);
    const int kuB = (lane >> 3) & 1;
    const int sw  = lane & 7;

    float acc[NT][4];
    #pragma unroll
    for (int t = 0; t < NT; t++)
        #pragma unroll
        for (int q = 0; q < 4; q++) acc[t][q] = 0.f;

    // ---- A chunk 0 into registers (overlaps the B wait below) ----
    float4 ra[8];
    #pragma unroll
    for (int j = 0; j < 4; j++) {
        ra[2 * j]     = *(const float4*)(aw + j * 16);
        ra[2 * j + 1] = *(const float4*)(aw + j * 16 + 20480);
    }

    // ---- load ALL of B into smem (one shot) ----
    // idx -> n = idx/64, q8 = idx%64; chunk kc = q8>>3, q = q8&7
    #pragma unroll
    for (int it = 0; it < CPIT; it++) {
        int idx = tid + it * 256;
        int n  = idx >> 6;
        int q8 = idx & 63;
        int kc = q8 >> 3;
        int q  = q8 & 7;
        uint32_t d = (uint32_t)(kc * BB + n * 128 + ((q ^ (n & 7)) << 4));
        cp16(su + d, BhT + n * 512 + q8 * 8);
    }
    asm volatile("cp.async.commit_group;" ::: "memory");
    asm volatile("cp.async.wait_group 0;" ::: "memory");
    __syncthreads();

    // ---- barrier-free mainloop: 8 chunks of 64 k ----
    #pragma unroll 1
    for (int kc = 0; kc < 8; kc++) {
        const uint32_t bBase = su + (uint32_t)(kc * BB);
        #pragma unroll
        for (int j = 0; j < 4; j++) {
            // convert current A fragment (permuted layout: float4 -> a0,a2)
            uint32_t ah[4];
            ah[0] = f16x2_rn(ra[2 * j].x,     ra[2 * j].y);
            ah[2] = f16x2_rn(ra[2 * j].z,     ra[2 * j].w);
            ah[1] = f16x2_rn(ra[2 * j + 1].x, ra[2 * j + 1].y);
            ah[3] = f16x2_rn(ra[2 * j + 1].z, ra[2 * j + 1].w);
            // refill this slot from chunk kc+1 (lookahead ~4 j-steps)
            if (kc < 7) {
                const float* ap = aw + (kc + 1) * 64 + j * 16;
                ra[2 * j]     = *(const float4*)(ap);
                ra[2 * j + 1] = *(const float4*)(ap + 20480);
            }
            // B fragments + MMAs
            uint32_t bu = (uint32_t)(((2 * j + kuB) ^ sw) << 4);
            #pragma unroll
            for (int p = 0; p < PAIRS; p++) {
                uint32_t boff = (uint32_t)((16 * p + rBo) * 128) + bu;
                uint32_t bh[4];
                ldsm_x4(bh, bBase + boff);
                mma_f16(acc[2 * p],     ah, bh);
                mma_f16(acc[2 * p + 1], ah, bh + 2);
            }
            if (ODD) {
                uint32_t boff = (uint32_t)((16 * PAIRS + (lane & 7)) * 128) + bu;
                uint32_t bh[2];
                ldsm_x2(bh, bBase + boff);
                mma_f16(acc[NT - 1], ah, bh);
            }
        }
    }

    // ---- epilogue: bias + scatter ----
    const int g   = lane >> 2;
    const int tig = lane & 3;

    int   coff[NT][2];
    float cb[NT][2];
    #pragma unroll
    for (int t = 0; t < NT; t++) {
        #pragma unroll
        for (int h = 0; h < 2; h++) {
            int o = CO + 8 * t + 2 * tig + h;
            if (o < NREAL) {
                int p   = o / (GS * 3);
                int rem = o - p * (GS * 3);
                int joff = (GS == 5) ? ((rem < 3) ? rem : rem + 18) : (jb3 + rem);
                coff[t][h] = p * 51 + joff;
                cb[t][h]   = bias[o];
            } else {
                coff[t][h] = -1;
                cb[t][h]   = 0.f;
            }
        }
    }

    #pragma unroll
    for (int half = 0; half < 2; half++) {
        int m  = m0 + 16 * wid + g + 8 * half;
        int b  = m / 27;
        int tp = m - b * 27;
        size_t obase = (size_t)b * 12393 + (size_t)tp * 459;
        #pragma unroll
        for (int t = 0; t < NT; t++) {
            float v0 = acc[t][2 * half];
            float v1 = acc[t][2 * half + 1];
            if (coff[t][0] >= 0) out[obase + coff[t][0]] = v0 + cb[t][0];
            if (coff[t][1] >= 0) out[obase + coff[t][1]] = v1 + cb[t][1];
        }
    }
}

// One fused kernel. blockIdx.x = variant: 0..3 -> groups 0,1,3,4 (NPAD=88);
// 4,5 -> group 2 halves (NPAD=72). blockIdx.y = m-block (same token rows
// across all 6 variants -> L2 reuse for g2 double-read + output merging).
__global__ void __launch_bounds__(256, 2) dec_all(
    const float* __restrict__ tokens,
    const float* __restrict__ b0, const float* __restrict__ b1,
    const float* __restrict__ b2, const float* __restrict__ b3,
    const float* __restrict__ b4,
    float* __restrict__ out)
{
    int y = blockIdx.x;
    if (y < 4) {
        int rowbase, gidx, jb3;
        const float* bias;
        switch (y) {
            case 0:  rowbase = 0;   gidx = 0; jb3 = 3;  bias = b0; break;
            case 1:  rowbase = 88;  gidx = 1; jb3 = 12; bias = b1; break;
            case 2:  rowbase = 320; gidx = 3; jb3 = 33; bias = b3; break;
            default: rowbase = 408; gidx = 4; jb3 = 42; bias = b4; break;
        }
        decode_core<88, 3, 0>(tokens, g_Bh + rowbase * 512, bias, out, gidx, jb3);
    } else if (y == 4) {
        decode_core<72, 5, 0>(tokens, g_Bh + 176 * 512, b2, out, 2, 0);
    } else {
        decode_core<72, 5, 72>(tokens, g_Bh + 248 * 512, b2, out, 2, 0);
    }
}

extern "C" void kernel_launch(void* const* d_in, const int* in_sizes, int n_in,
                              void* d_out, int out_size) {
    const float* tokens = (const float*)d_in[0];
    const float* W[5];
    const float* B[5];
    for (int i = 0; i < 5; i++) {
        W[i] = (const float*)d_in[1 + 2 * i];
        B[i] = (const float*)d_in[2 + 2 * i];
    }
    float* out = (float*)d_out;

    // dyn smem: whole B = 8 * NPAD * 128 bytes; max NPAD=88 -> 90112 B.
    // 2 CTAs/SM x 90112 = 180224 <= 228KB.
    const int smem_sz = 8 * 88 * 128;
    cudaFuncSetAttribute(dec_all, cudaFuncAttributeMaxDynamicSharedMemorySize, smem_sz);

    prep_B<<<(496 * 128 + 255) / 256, 256>>>(W[0], W[1], W[2], W[3], W[4]);
    dec_all<<<dim3(6, 216), 256, smem_sz>>>(tokens, B[0], B[1], B[2], B[3], B[4], out);
}